// round 16
// baseline (speedup 1.0000x reference)
#include <cuda_runtime.h>
#include <cuda_fp16.h>
#include <math.h>

#define T_TOTAL 32768
#define NEXP    64
#define HDIM    1024
#define GRID    592            // 4 CTAs/SM, one wave
#define NTHR    128
#define KC      64
#define NCHUNK  (HDIM / KC)    // 16
#define EPS_TIE 8e-4f
#define TROWS   64             // tokens per CTA (<= 64 actual: 55..56)

#define A_LEV   8192           // 64 rows x 128B (fp16)
#define A_BYTES (2 * A_LEV)    // double buffered: 16KB
#define B_CHUNK 8192           // 4 s x 4 npair x 32 lanes x 16B
#define B_BYTES (2 * B_CHUNK)  // 16KB double buffer
#define SMEM_REQ (A_BYTES + B_BYTES)   // 32KB

// W as fp16, stored in mma B-fragment register order
__device__ unsigned char g_Wfrag[NCHUNK * B_CHUNK];

// one thread per 16B fragment group: g = ((chunk*4+s)*4+npair)*32+lane
__global__ void prep_w_kernel(const float* __restrict__ W) {
    int g = blockIdx.x * blockDim.x + threadIdx.x;
    if (g >= NCHUNK * 512) return;
    int lane = g & 31;
    int t = g >> 5;
    int npair = t & 3;  t >>= 2;
    int s = t & 3;
    int chunk = t >> 2;
    int k0 = chunk * KC + s * 16 + (lane & 3) * 2;
    unsigned w[4];
#pragma unroll
    for (int q = 0; q < 2; q++) {
        int e = (npair * 2 + q) * 8 + (lane >> 2);
        const float* We = W + (size_t)e * HDIM;
        w[q * 2 + 0] = (unsigned)__half_as_ushort(__float2half_rn(We[k0]))
                     | ((unsigned)__half_as_ushort(__float2half_rn(We[k0 + 1])) << 16);
        w[q * 2 + 1] = (unsigned)__half_as_ushort(__float2half_rn(We[k0 + 8]))
                     | ((unsigned)__half_as_ushort(__float2half_rn(We[k0 + 9])) << 16);
    }
    *(uint4*)&g_Wfrag[(size_t)g * 16] = make_uint4(w[0], w[1], w[2], w[3]);
}

#define CP_ASYNC16(dst_u32, src) \
    asm volatile("cp.async.cg.shared.global [%0], [%1], 16;" :: "r"(dst_u32), "l"(src))
#define CP_COMMIT()  asm volatile("cp.async.commit_group;")
#define CP_WAIT0()   asm volatile("cp.async.wait_group 0;")

#define LDMATRIX_X4(a, addr)                                            \
    asm volatile("ldmatrix.sync.aligned.m8n8.x4.shared.b16 {%0,%1,%2,%3}, [%4];" \
        : "=r"((a)[0]), "=r"((a)[1]), "=r"((a)[2]), "=r"((a)[3]) : "r"(addr))

#define MMA_F16(d, a, b0, b1)                                           \
    asm volatile("mma.sync.aligned.m16n8k16.row.col.f32.f16.f16.f32 "   \
        "{%0,%1,%2,%3}, {%4,%5,%6,%7}, {%8,%9}, {%0,%1,%2,%3};"         \
        : "+f"((d)[0]), "+f"((d)[1]), "+f"((d)[2]), "+f"((d)[3])        \
        : "r"((a)[0]), "r"((a)[1]), "r"((a)[2]), "r"((a)[3]), "r"(b0), "r"(b1))

__global__ __launch_bounds__(NTHR, 4)
void moe_gate_mma(const float* __restrict__ x,
                  const float* __restrict__ W,
                  float* __restrict__ out,
                  int out_size)
{
    extern __shared__ unsigned char dsm[];
    const unsigned smemA = (unsigned)__cvta_generic_to_shared(dsm);
    const unsigned smemB = smemA + A_BYTES;

    __shared__ int s_nflag;
    __shared__ int s_rows[TROWS];

    const int tid  = threadIdx.x;
    const int w    = tid >> 5;
    const int lane = tid & 31;
    const int wm   = w & 1;           // 2 m-tiles of 32 rows
    const int wn   = w >> 1;          // 2 n-halves of 32 experts
    const int m_base = wm * 32;
    const int n_base = wn * 32;
    const int np0  = wn * 2;

    const int start = (int)(((long long)blockIdx.x * T_TOTAL) / GRID);
    const int count = (int)(((long long)(blockIdx.x + 1) * T_TOTAL) / GRID) - start;
    const float* xblk = x + (size_t)start * HDIM;

    if (tid == 0) s_nflag = 0;

    float acc[2][4][4];
#pragma unroll
    for (int mt = 0; mt < 2; mt++)
#pragma unroll
        for (int nt = 0; nt < 4; nt++)
#pragma unroll
            for (int i = 0; i < 4; i++) acc[mt][nt][i] = 0.0f;

    float4 xr[8];

    auto ldg_x = [&](int c) {
#pragma unroll
        for (int i = 0; i < 8; i++) {
            int idx = i * NTHR + tid;          // 1024 = 64 rows x 16 float4
            int row = idx >> 4, c4 = idx & 15;
            int gr = (row < count) ? row : 0;
            xr[i] = *(const float4*)&xblk[(size_t)gr * HDIM + c * KC + c4 * 4];
        }
    };

    // convert xr -> fp16, store into A buffer `buf` (swizzled)
    auto sts_a = [&](int buf) {
        unsigned char* base = dsm + buf * A_LEV;
#pragma unroll
        for (int i = 0; i < 8; i++) {
            int idx = i * NTHR + tid;
            int row = idx >> 4, c4 = idx & 15;
            unsigned off = (unsigned)(row * 128)
                         + (((unsigned)((c4 >> 1) ^ (row & 7)) << 4) | ((c4 & 1) << 3));
            float4 v = xr[i];
            __half2 h01 = __floats2half2_rn(v.x, v.y);   // v.x in low half
            __half2 h23 = __floats2half2_rn(v.z, v.w);
            *(uint2*)(base + off) = make_uint2(
                *(unsigned*)&h01, *(unsigned*)&h23);
        }
    };

    auto cp_b = [&](int c) {
        unsigned dbase = smemB + (c & 1) * B_CHUNK;
        const unsigned char* src = g_Wfrag + (size_t)c * B_CHUNK;
#pragma unroll
        for (int i = 0; i < 4; i++) {
            int idx = i * NTHR + tid;          // 512 x 16B
            CP_ASYNC16(dbase + idx * 16, src + (size_t)idx * 16);
        }
    };

    // prologue: A(0) staged, x(1) in regs, B(0) resident before barrier
    ldg_x(0);
    cp_b(0); CP_COMMIT();
    sts_a(0);
    ldg_x(1);
    CP_WAIT0();
    __syncthreads();

    for (int c = 0; c < NCHUNK; c++) {
        if (c + 1 < NCHUNK) { cp_b(c + 1); CP_COMMIT(); }

        const unsigned abase = smemA + (c & 1) * A_LEV;
        const unsigned bbase = smemB + (c & 1) * B_CHUNK;

#pragma unroll
        for (int s = 0; s < 4; s++) {
            unsigned a[2][4];
#pragma unroll
            for (int mt = 0; mt < 2; mt++) {
                int arow = m_base + mt * 16 + ((lane >> 3) & 1) * 8 + (lane & 7);
                unsigned addr = abase + arow * 128
                    + ((unsigned)(((s << 1) | ((lane >> 4) & 1)) ^ (arow & 7)) << 4);
                LDMATRIX_X4(a[mt], addr);
            }
            unsigned boff = bbase + ((s * 4 + np0) * 512) + lane * 16;
            uint4 b0, b1;
            asm volatile("ld.shared.v4.u32 {%0,%1,%2,%3}, [%4];"
                : "=r"(b0.x), "=r"(b0.y), "=r"(b0.z), "=r"(b0.w) : "r"(boff));
            asm volatile("ld.shared.v4.u32 {%0,%1,%2,%3}, [%4];"
                : "=r"(b1.x), "=r"(b1.y), "=r"(b1.z), "=r"(b1.w) : "r"(boff + 512));
#pragma unroll
            for (int mt = 0; mt < 2; mt++) {
                MMA_F16(acc[mt][0], a[mt], b0.x, b0.y);
                MMA_F16(acc[mt][1], a[mt], b0.z, b0.w);
                MMA_F16(acc[mt][2], a[mt], b1.x, b1.y);
                MMA_F16(acc[mt][3], a[mt], b1.z, b1.w);
            }
        }

        if (c + 1 < NCHUNK) sts_a((c + 1) & 1);   // buffer last read in chunk c-1
        if (c + 2 < NCHUNK) ldg_x(c + 2);
        if (c + 1 < NCHUNK) CP_WAIT0();           // everyone's B(c+1) retired pre-barrier
        __syncthreads();
    }

    // ---------------- epilogue ----------------
    float* L = (float*)dsm;   // pitch 68 floats, conflict-free (64 rows -> 17.4KB)
    {
        int r0l = lane >> 2, c0l = (lane & 3) * 2;
#pragma unroll
        for (int mt = 0; mt < 2; mt++)
#pragma unroll
            for (int nt = 0; nt < 4; nt++) {
                int row = m_base + mt * 16 + r0l;
                int col = n_base + nt * 8 + c0l;
                *(float2*)&L[row * 68 + col]       = make_float2(acc[mt][nt][0], acc[mt][nt][1]);
                *(float2*)&L[(row + 8) * 68 + col] = make_float2(acc[mt][nt][2], acc[mt][nt][3]);
            }
    }
    __syncthreads();

    // --- phase 1: flag near-tie rows (top-3 gap test) ---
    if (tid < TROWS && tid < count) {
        int row = tid;
        float v1 = -INFINITY, v2 = -INFINITY, v3 = -INFINITY;
#pragma unroll
        for (int e = 0; e < NEXP; e++) {
            float lv = L[row * 68 + e];
            if (lv > v1)      { v3 = v2; v2 = v1; v1 = lv; }
            else if (lv > v2) { v3 = v2; v2 = lv; }
            else if (lv > v3) { v3 = lv; }
        }
        if (v1 - v2 < EPS_TIE || v2 - v3 < EPS_TIE) {
            int slot = atomicAdd(&s_nflag, 1);
            s_rows[slot] = row;
        }
    }
    __syncthreads();

    // --- phase 2: cooperative exact-fp32 recompute of flagged rows ---
    // Coalesced: warp w owns experts 16w..16w+15; lanes split k contiguously.
    {
        const int nf = s_nflag;
        for (int f = 0; f < nf; f++) {
            int row = s_rows[f];
            const float* xrow = xblk + (size_t)row * HDIM;
#pragma unroll
            for (int ei = 0; ei < 16; ei++) {
                int e = w * 16 + ei;
                const float* We = W + (size_t)e * HDIM;
                float d0 = 0.f, d1 = 0.f, d2 = 0.f, d3 = 0.f;
#pragma unroll
                for (int kk = 0; kk < 8; kk++) {
                    int off = (kk * 32 + lane) * 4;
                    float4 xa = *(const float4*)&xrow[off];
                    float4 wa = *(const float4*)&We[off];
                    d0 = fmaf(xa.x, wa.x, d0);
                    d1 = fmaf(xa.y, wa.y, d1);
                    d2 = fmaf(xa.z, wa.z, d2);
                    d3 = fmaf(xa.w, wa.w, d3);
                }
                float v = (d0 + d1) + (d2 + d3);
                v += __shfl_xor_sync(0xffffffffu, v, 16);
                v += __shfl_xor_sync(0xffffffffu, v, 8);
                v += __shfl_xor_sync(0xffffffffu, v, 4);
                v += __shfl_xor_sync(0xffffffffu, v, 2);
                v += __shfl_xor_sync(0xffffffffu, v, 1);
                if (lane == 0) L[row * 68 + e] = v;
            }
        }
        if (nf) __syncthreads();
    }

    // --- phase 3: softmax + top-2 from (possibly corrected) logits ---
    if (tid < TROWS && tid < count) {
        int row = tid;
        float l[64];
#pragma unroll
        for (int i = 0; i < 16; i++)
            *(float4*)&l[i * 4] = *(const float4*)&L[row * 68 + i * 4];

        float mx = l[0];
#pragma unroll
        for (int e = 1; e < NEXP; e++) mx = fmaxf(mx, l[e]);
        float sum = 0.0f;
#pragma unroll
        for (int e = 0; e < NEXP; e++) sum += expf(l[e] - mx);

        float v1 = -INFINITY, v2 = -INFINITY;
        int   i1 = 0, i2 = 0;
#pragma unroll
        for (int e = 0; e < NEXP; e++) {
            float lv = l[e];
            if (lv > v1)      { v2 = v1; i2 = i1; v1 = lv; i1 = e; }
            else if (lv > v2) { v2 = lv; i2 = e; }
        }

        float p1 = expf(v1 - mx) / sum;
        float p2 = expf(v2 - mx) / sum;
        float e21 = expf(p2 - p1);
        float s1  = 1.0f / (1.0f + e21);
        float s2  = e21 * s1;

        int t = start + row;
        *(float2*)&out[2 * (size_t)t] = make_float2(s1, s2);
        *(float2*)&out[2 * (size_t)T_TOTAL + 2 * (size_t)t] =
            make_float2((float)i1, (float)i2);
    }

    // tail (scalar zero output + anything past 4*T)
    if (blockIdx.x == 0 && tid < 32) {
        for (int p = 4 * T_TOTAL + tid; p < out_size; p += 32)
            out[p] = 0.0f;
    }
}

extern "C" void kernel_launch(void* const* d_in, const int* in_sizes, int n_in,
                              void* d_out, int out_size)
{
    const float* x = (const float*)d_in[0];
    const float* W = (const float*)d_in[1];
    float* out = (float*)d_out;

    static bool attr_set = false;
    if (!attr_set) {
        cudaFuncSetAttribute(moe_gate_mma,
                             cudaFuncAttributeMaxDynamicSharedMemorySize, SMEM_REQ);
        attr_set = true;
    }

    prep_w_kernel<<<(NCHUNK * 512 + 255) / 256, 256>>>(W);
    moe_gate_mma<<<GRID, NTHR, SMEM_REQ>>>(x, W, out, out_size);
}

// round 17
// speedup vs baseline: 1.1506x; 1.1506x over previous
#include <cuda_runtime.h>
#include <cuda_fp16.h>
#include <math.h>

#define T_TOTAL 32768
#define NEXP    64
#define HDIM    1024
#define GRID    296            // 2 CTAs/SM, one wave
#define NTHR    256
#define NPAIR   8              // 8 pairs x 128 k
#define EPS_TIE 8e-4f

#define A_SUB   16384          // 128 rows x 128B fp16 (64 k)
#define A_BUF   (2 * A_SUB)    // 32KB per pair-buffer
#define A_BYTES (2 * A_BUF)    // 64KB double buffered
#define B_SUB   8192           // per 64-k chunk
#define B_PAIR  (2 * B_SUB)    // 16KB
#define B_BYTES (2 * B_PAIR)   // 32KB double buffered
#define SMEM_REQ (A_BYTES + B_BYTES)   // 96KB

// W as fp16, stored in mma B-fragment register order (by 64-k chunk)
__device__ unsigned char g_Wfrag[16 * B_SUB];

// one thread per 16B fragment group: g = ((chunk*4+s)*4+npair)*32+lane
__global__ void prep_w_kernel(const float* __restrict__ W) {
    int g = blockIdx.x * blockDim.x + threadIdx.x;
    if (g >= 16 * 512) return;
    int lane = g & 31;
    int t = g >> 5;
    int npair = t & 3;  t >>= 2;
    int s = t & 3;
    int chunk = t >> 2;
    int k0 = chunk * 64 + s * 16 + (lane & 3) * 2;
    unsigned w[4];
#pragma unroll
    for (int q = 0; q < 2; q++) {
        int e = (npair * 2 + q) * 8 + (lane >> 2);
        const float* We = W + (size_t)e * HDIM;
        w[q * 2 + 0] = (unsigned)__half_as_ushort(__float2half_rn(We[k0]))
                     | ((unsigned)__half_as_ushort(__float2half_rn(We[k0 + 1])) << 16);
        w[q * 2 + 1] = (unsigned)__half_as_ushort(__float2half_rn(We[k0 + 8]))
                     | ((unsigned)__half_as_ushort(__float2half_rn(We[k0 + 9])) << 16);
    }
    *(uint4*)&g_Wfrag[(size_t)g * 16] = make_uint4(w[0], w[1], w[2], w[3]);
}

#define CP_ASYNC16(dst_u32, src) \
    asm volatile("cp.async.cg.shared.global [%0], [%1], 16;" :: "r"(dst_u32), "l"(src))
#define CP_COMMIT()  asm volatile("cp.async.commit_group;")
#define CP_WAIT0()   asm volatile("cp.async.wait_group 0;")

#define LDMATRIX_X4(a, addr)                                            \
    asm volatile("ldmatrix.sync.aligned.m8n8.x4.shared.b16 {%0,%1,%2,%3}, [%4];" \
        : "=r"((a)[0]), "=r"((a)[1]), "=r"((a)[2]), "=r"((a)[3]) : "r"(addr))

#define MMA_F16(d, a, b0, b1)                                           \
    asm volatile("mma.sync.aligned.m16n8k16.row.col.f32.f16.f16.f32 "   \
        "{%0,%1,%2,%3}, {%4,%5,%6,%7}, {%8,%9}, {%0,%1,%2,%3};"         \
        : "+f"((d)[0]), "+f"((d)[1]), "+f"((d)[2]), "+f"((d)[3])        \
        : "r"((a)[0]), "r"((a)[1]), "r"((a)[2]), "r"((a)[3]), "r"(b0), "r"(b1))

__global__ __launch_bounds__(NTHR, 2)
void moe_gate_mma(const float* __restrict__ x,
                  const float* __restrict__ W,
                  float* __restrict__ out,
                  int out_size)
{
    extern __shared__ unsigned char dsm[];
    const unsigned smemA = (unsigned)__cvta_generic_to_shared(dsm);
    const unsigned smemB = smemA + A_BYTES;

    __shared__ int s_nflag;
    __shared__ int s_rows[128];

    const int tid  = threadIdx.x;
    const int w    = tid >> 5;
    const int lane = tid & 31;
    const int wm   = w & 3;           // 4 m-tiles of 32 rows
    const int wn   = w >> 2;          // 2 n-halves of 32 experts
    const int m_base = wm * 32;
    const int n_base = wn * 32;
    const int np0  = wn * 2;

    const int start = (int)(((long long)blockIdx.x * T_TOTAL) / GRID);
    const int count = (int)(((long long)(blockIdx.x + 1) * T_TOTAL) / GRID) - start;
    const float* xblk = x + (size_t)start * HDIM;

    if (tid == 0) s_nflag = 0;

    float acc[2][4][4];
#pragma unroll
    for (int mt = 0; mt < 2; mt++)
#pragma unroll
        for (int nt = 0; nt < 4; nt++)
#pragma unroll
            for (int i = 0; i < 4; i++) acc[mt][nt][i] = 0.0f;

    float4 xr[8];

    // load one 64-k half-chunk (chunk index c64 in [0,16)) into xr
    auto ldg_half = [&](int c64) {
#pragma unroll
        for (int i = 0; i < 8; i++) {
            int idx = i * NTHR + tid;          // 2048 = 128 rows x 16 float4
            int row = idx >> 4, c4 = idx & 15;
            int gr = (row < count) ? row : 0;
            xr[i] = *(const float4*)&xblk[(size_t)gr * HDIM + c64 * 64 + c4 * 4];
        }
    };

    // convert xr -> fp16 into pair-buffer `pbuf`, sub-tile h
    auto sts_half = [&](int pbuf, int h) {
        unsigned char* base = dsm + pbuf * A_BUF + h * A_SUB;
#pragma unroll
        for (int i = 0; i < 8; i++) {
            int idx = i * NTHR + tid;
            int row = idx >> 4, c4 = idx & 15;
            unsigned off = (unsigned)(row * 128)
                         + (((unsigned)((c4 >> 1) ^ (row & 7)) << 4) | ((c4 & 1) << 3));
            float4 v = xr[i];
            __half2 h01 = __floats2half2_rn(v.x, v.y);
            __half2 h23 = __floats2half2_rn(v.z, v.w);
            *(uint2*)(base + off) = make_uint2(*(unsigned*)&h01, *(unsigned*)&h23);
        }
    };

    // copy both B sub-chunks of pair p
    auto cp_b2 = [&](int p) {
        unsigned dbase = smemB + (p & 1) * B_PAIR;
        const unsigned char* src = g_Wfrag + (size_t)p * B_PAIR;
#pragma unroll
        for (int i = 0; i < 4; i++) {
            int idx = i * NTHR + tid;          // 1024 x 16B
            CP_ASYNC16(dbase + idx * 16, src + (size_t)idx * 16);
        }
    };

    // compute s-steps [s0, s1) of pair-buffer pbuf
    auto compute = [&](int pbuf, int s0, int s1) {
        const unsigned abase = smemA + pbuf * A_BUF;
        const unsigned bbase = smemB + pbuf * B_PAIR;
        for (int s = s0; s < s1; s++) {
            const unsigned asub = abase + (s >> 2) * A_SUB;
            const unsigned bsub = bbase + (s >> 2) * B_SUB;
            const int sq = s & 3;
            unsigned a[2][4];
#pragma unroll
            for (int mt = 0; mt < 2; mt++) {
                int arow = m_base + mt * 16 + ((lane >> 3) & 1) * 8 + (lane & 7);
                unsigned addr = asub + arow * 128
                    + ((unsigned)(((sq << 1) | ((lane >> 4) & 1)) ^ (arow & 7)) << 4);
                LDMATRIX_X4(a[mt], addr);
            }
            unsigned boff = bsub + ((sq * 4 + np0) * 512) + lane * 16;
            uint4 b0, b1;
            asm volatile("ld.shared.v4.u32 {%0,%1,%2,%3}, [%4];"
                : "=r"(b0.x), "=r"(b0.y), "=r"(b0.z), "=r"(b0.w) : "r"(boff));
            asm volatile("ld.shared.v4.u32 {%0,%1,%2,%3}, [%4];"
                : "=r"(b1.x), "=r"(b1.y), "=r"(b1.z), "=r"(b1.w) : "r"(boff + 512));
#pragma unroll
            for (int mt = 0; mt < 2; mt++) {
                MMA_F16(acc[mt][0], a[mt], b0.x, b0.y);
                MMA_F16(acc[mt][1], a[mt], b0.z, b0.w);
                MMA_F16(acc[mt][2], a[mt], b1.x, b1.y);
                MMA_F16(acc[mt][3], a[mt], b1.z, b1.w);
            }
        }
    };

    // prologue: A(pair0) staged, xr = H0(pair1), B(pair0) resident
    ldg_half(0);
    cp_b2(0); CP_COMMIT();
    sts_half(0, 0);
    ldg_half(1);
    sts_half(0, 1);
    ldg_half(2);                     // H0 of pair 1
    CP_WAIT0();
    __syncthreads();

    for (int p = 0; p < NPAIR; p++) {
        const int pbuf = p & 1;
        const int nbuf = (p + 1) & 1;

        if (p + 1 < NPAIR) {
            cp_b2(p + 1); CP_COMMIT();
            sts_half(nbuf, 0);              // xr = H0(p+1), staged now
            ldg_half(2 * (p + 1) + 1);      // H1(p+1)
        }

        compute(pbuf, 0, 6);

        if (p + 1 < NPAIR) sts_half(nbuf, 1);       // H1(p+1), ldg 6 s-steps ago
        if (p + 2 < NPAIR) ldg_half(2 * (p + 2));   // H0(p+2)

        compute(pbuf, 6, 8);

        if (p + 1 < NPAIR) CP_WAIT0();      // B(p+1) retired before barrier
        __syncthreads();
    }

    // ---------------- epilogue ----------------
    float* L = (float*)dsm;   // pitch 68 floats, conflict-free
    {
        int r0l = lane >> 2, c0l = (lane & 3) * 2;
#pragma unroll
        for (int mt = 0; mt < 2; mt++)
#pragma unroll
            for (int nt = 0; nt < 4; nt++) {
                int row = m_base + mt * 16 + r0l;
                int col = n_base + nt * 8 + c0l;
                *(float2*)&L[row * 68 + col]       = make_float2(acc[mt][nt][0], acc[mt][nt][1]);
                *(float2*)&L[(row + 8) * 68 + col] = make_float2(acc[mt][nt][2], acc[mt][nt][3]);
            }
    }
    __syncthreads();

    // --- phase 1: flag near-tie rows (top-3 gap test) ---
    if (tid < 128 && tid < count) {
        int row = tid;
        float v1 = -INFINITY, v2 = -INFINITY, v3 = -INFINITY;
#pragma unroll
        for (int e = 0; e < NEXP; e++) {
            float lv = L[row * 68 + e];
            if (lv > v1)      { v3 = v2; v2 = v1; v1 = lv; }
            else if (lv > v2) { v3 = v2; v2 = lv; }
            else if (lv > v3) { v3 = lv; }
        }
        if (v1 - v2 < EPS_TIE || v2 - v3 < EPS_TIE) {
            int slot = atomicAdd(&s_nflag, 1);
            s_rows[slot] = row;
        }
    }
    __syncthreads();

    // --- phase 2: cooperative exact-fp32 recompute of flagged rows ---
    // Coalesced: warp w owns experts 8w..8w+7; lanes split k contiguously.
    {
        const int nf = s_nflag;
        for (int f = 0; f < nf; f++) {
            int row = s_rows[f];
            const float* xrow = xblk + (size_t)row * HDIM;
#pragma unroll
            for (int ei = 0; ei < 8; ei++) {
                int e = w * 8 + ei;
                const float* We = W + (size_t)e * HDIM;
                float d0 = 0.f, d1 = 0.f, d2 = 0.f, d3 = 0.f;
#pragma unroll
                for (int kk = 0; kk < 8; kk++) {
                    int off = (kk * 32 + lane) * 4;
                    float4 xa = *(const float4*)&xrow[off];
                    float4 wa = *(const float4*)&We[off];
                    d0 = fmaf(xa.x, wa.x, d0);
                    d1 = fmaf(xa.y, wa.y, d1);
                    d2 = fmaf(xa.z, wa.z, d2);
                    d3 = fmaf(xa.w, wa.w, d3);
                }
                float v = (d0 + d1) + (d2 + d3);
                v += __shfl_xor_sync(0xffffffffu, v, 16);
                v += __shfl_xor_sync(0xffffffffu, v, 8);
                v += __shfl_xor_sync(0xffffffffu, v, 4);
                v += __shfl_xor_sync(0xffffffffu, v, 2);
                v += __shfl_xor_sync(0xffffffffu, v, 1);
                if (lane == 0) L[row * 68 + e] = v;
            }
        }
        if (nf) __syncthreads();
    }

    // --- phase 3: softmax + top-2 from (possibly corrected) logits ---
    if (tid < 128 && tid < count) {
        int row = tid;
        float l[64];
#pragma unroll
        for (int i = 0; i < 16; i++)
            *(float4*)&l[i * 4] = *(const float4*)&L[row * 68 + i * 4];

        float mx = l[0];
#pragma unroll
        for (int e = 1; e < NEXP; e++) mx = fmaxf(mx, l[e]);
        float sum = 0.0f;
#pragma unroll
        for (int e = 0; e < NEXP; e++) sum += expf(l[e] - mx);

        float v1 = -INFINITY, v2 = -INFINITY;
        int   i1 = 0, i2 = 0;
#pragma unroll
        for (int e = 0; e < NEXP; e++) {
            float lv = l[e];
            if (lv > v1)      { v2 = v1; i2 = i1; v1 = lv; i1 = e; }
            else if (lv > v2) { v2 = lv; i2 = e; }
        }

        float p1 = expf(v1 - mx) / sum;
        float p2 = expf(v2 - mx) / sum;
        float e21 = expf(p2 - p1);
        float s1  = 1.0f / (1.0f + e21);
        float s2  = e21 * s1;

        int t = start + row;
        *(float2*)&out[2 * (size_t)t] = make_float2(s1, s2);
        *(float2*)&out[2 * (size_t)T_TOTAL + 2 * (size_t)t] =
            make_float2((float)i1, (float)i2);
    }

    // tail (scalar zero output + anything past 4*T)
    if (blockIdx.x == 0 && tid < 32) {
        for (int p = 4 * T_TOTAL + tid; p < out_size; p += 32)
            out[p] = 0.0f;
    }
}

extern "C" void kernel_launch(void* const* d_in, const int* in_sizes, int n_in,
                              void* d_out, int out_size)
{
    const float* x = (const float*)d_in[0];
    const float* W = (const float*)d_in[1];
    float* out = (float*)d_out;

    static bool attr_set = false;
    if (!attr_set) {
        cudaFuncSetAttribute(moe_gate_mma,
                             cudaFuncAttributeMaxDynamicSharedMemorySize, SMEM_REQ);
        attr_set = true;
    }

    prep_w_kernel<<<32, 256>>>(W);
    moe_gate_mma<<<GRID, NTHR, SMEM_REQ>>>(x, W, out, out_size);
}